// round 1
// baseline (speedup 1.0000x reference)
#include <cuda_runtime.h>
#include <math.h>

#define B 64
#define N 1024
#define F_IN 64
#define E 128
#define TOPK 32
#define NEG_SLOPE 0.2f

// ---------------- scratch (device globals; no allocation allowed) ----------
__device__ __align__(16) float g_h[B * N * E];     // 32 MB
__device__ float g_es[B * N];
__device__ float g_ed[B * N];
__device__ __align__(16) float g_embn[N * E];      // normalized emb
__device__ float g_eemb_s[N];
__device__ float g_eemb_d[N];
__device__ float g_ws[2 * F_IN];                   // [ws_src | ws_dst]
__device__ int   g_idx[N * TOPK];

// ---------------- K0: ws_src[f] = sum_e W_fe[f,e]*a_src[e]  (and dst) ------
__global__ void k0_ws(const float* __restrict__ Wfe,
                      const float* __restrict__ a_src,
                      const float* __restrict__ a_dst) {
    int t = threadIdx.x;  // 128 threads
    if (t < F_IN) {
        float s = 0.f;
        #pragma unroll 8
        for (int e = 0; e < E; e++) s += Wfe[t * E + e] * a_src[e];
        g_ws[t] = s;
    } else {
        int f = t - F_IN;
        float s = 0.f;
        #pragma unroll 8
        for (int e = 0; e < E; e++) s += Wfe[f * E + e] * a_dst[e];
        g_ws[F_IN + f] = s;
    }
}

// ---------------- K1a: normalize emb rows + emb-side attention dots --------
__global__ void k1a_norm(const float* __restrict__ emb,
                         const float* __restrict__ a_src,
                         const float* __restrict__ a_dst) {
    int n = blockIdx.x;
    int e = threadIdx.x;  // 128
    int lane = e & 31, wid = e >> 5;
    __shared__ float sm[12];
    float v  = emb[n * E + e];
    float r0 = v * v;
    float r1 = v * a_src[E + e];
    float r2 = v * a_dst[E + e];
    #pragma unroll
    for (int o = 16; o; o >>= 1) {
        r0 += __shfl_xor_sync(0xffffffffu, r0, o);
        r1 += __shfl_xor_sync(0xffffffffu, r1, o);
        r2 += __shfl_xor_sync(0xffffffffu, r2, o);
    }
    if (lane == 0) { sm[wid] = r0; sm[4 + wid] = r1; sm[8 + wid] = r2; }
    __syncthreads();
    float sumsq = sm[0] + sm[1] + sm[2] + sm[3];
    g_embn[n * E + e] = v * rsqrtf(sumsq);
    if (e == 0) {
        g_eemb_s[n] = sm[4] + sm[5] + sm[6] + sm[7];
        g_eemb_d[n] = sm[8] + sm[9] + sm[10] + sm[11];
    }
}

// ---------------- K1b: cosine sim rows + top-32 (set semantics) ------------
#define ROWS 8
__global__ void k1b_topk() {
    __shared__ __align__(16) float q[ROWS * E];     // 4 KB
    __shared__ float sims[ROWS][N];                 // 32 KB
    int tid = threadIdx.x;                           // 256
    int row0 = blockIdx.x * ROWS;

    for (int i = tid; i < ROWS * E; i += 256) q[i] = g_embn[row0 * E + i];
    __syncthreads();

    const float4* q4 = (const float4*)q;
    const float4* g4 = (const float4*)g_embn;

    for (int c = tid; c < N; c += 256) {
        float acc[ROWS];
        #pragma unroll
        for (int r = 0; r < ROWS; r++) acc[r] = 0.f;
        const float4* rp = g4 + (size_t)c * (E / 4);
        #pragma unroll 4
        for (int j = 0; j < E / 4; j++) {
            float4 rv = rp[j];
            #pragma unroll
            for (int r = 0; r < ROWS; r++) {
                float4 qv = q4[r * (E / 4) + j];
                acc[r] += rv.x * qv.x + rv.y * qv.y + rv.z * qv.z + rv.w * qv.w;
            }
        }
        #pragma unroll
        for (int r = 0; r < ROWS; r++) sims[r][c] = acc[r];
    }
    __syncthreads();

    int wid = tid >> 5, lane = tid & 31;
    if (wid < ROWS) {
        int r = wid;
        for (int round = 0; round < TOPK; round++) {
            float bv = -INFINITY; int bi = N;
            for (int c = lane; c < N; c += 32) {
                float v = sims[r][c];
                if (v > bv || (v == bv && c < bi)) { bv = v; bi = c; }
            }
            #pragma unroll
            for (int o = 16; o; o >>= 1) {
                float ov = __shfl_xor_sync(0xffffffffu, bv, o);
                int   oi = __shfl_xor_sync(0xffffffffu, bi, o);
                if (ov > bv || (ov == bv && oi < bi)) { bv = ov; bi = oi; }
            }
            if (lane == 0) {
                g_idx[(row0 + r) * TOPK + round] = bi;
                sims[r][bi] = -INFINITY;
            }
            __syncwarp();
        }
    }
}

// ---------------- K2: h = x @ W_fe ; e_s/e_d per token ---------------------
#define TOKB 16
__global__ void k2_h(const float* __restrict__ x,
                     const float* __restrict__ Wfe) {
    __shared__ __align__(16) float Ws[F_IN * E];     // 32 KB
    __shared__ __align__(16) float xs[TOKB * F_IN];  // 4 KB
    __shared__ float ws[2 * F_IN];
    int tid = threadIdx.x;  // 128
    int t0 = blockIdx.x * TOKB;

    {   // cooperative loads
        float4* Wd = (float4*)Ws;
        const float4* Wsrc = (const float4*)Wfe;
        #pragma unroll
        for (int i = 0; i < (F_IN * E / 4) / 128; i++)
            Wd[tid + i * 128] = Wsrc[tid + i * 128];
        float4* xd = (float4*)xs;
        const float4* xsrc = (const float4*)(x + (size_t)t0 * F_IN);
        #pragma unroll
        for (int i = 0; i < (TOKB * F_IN / 4) / 128; i++)
            xd[tid + i * 128] = xsrc[tid + i * 128];
        ws[tid] = g_ws[tid];
    }
    __syncthreads();

    int te = tid & 31;   // e-group: covers e in [te*4, te*4+4)
    int tt = tid >> 5;   // token group: tokens tt*4 .. tt*4+3
    const float4* W4 = (const float4*)Ws;

    float4 acc0 = {0,0,0,0}, acc1 = {0,0,0,0}, acc2 = {0,0,0,0}, acc3 = {0,0,0,0};
    #pragma unroll 8
    for (int f = 0; f < F_IN; f++) {
        float4 w = W4[f * 32 + te];
        float x0 = xs[(tt * 4 + 0) * F_IN + f];
        float x1 = xs[(tt * 4 + 1) * F_IN + f];
        float x2 = xs[(tt * 4 + 2) * F_IN + f];
        float x3 = xs[(tt * 4 + 3) * F_IN + f];
        acc0.x += x0 * w.x; acc0.y += x0 * w.y; acc0.z += x0 * w.z; acc0.w += x0 * w.w;
        acc1.x += x1 * w.x; acc1.y += x1 * w.y; acc1.z += x1 * w.z; acc1.w += x1 * w.w;
        acc2.x += x2 * w.x; acc2.y += x2 * w.y; acc2.z += x2 * w.z; acc2.w += x2 * w.w;
        acc3.x += x3 * w.x; acc3.y += x3 * w.y; acc3.z += x3 * w.z; acc3.w += x3 * w.w;
    }
    float4* h4 = (float4*)g_h;
    size_t base = (size_t)(t0 + tt * 4) * (E / 4) + te;
    h4[base + 0 * (E / 4)] = acc0;
    h4[base + 1 * (E / 4)] = acc1;
    h4[base + 2 * (E / 4)] = acc2;
    h4[base + 3 * (E / 4)] = acc3;

    // e_s / e_d for the block's 16 tokens
    if (tid < TOKB) {
        int gt = t0 + tid;
        int n = gt & (N - 1);
        float s = 0.f, d = 0.f;
        #pragma unroll 8
        for (int f = 0; f < F_IN; f++) {
            float xv = xs[tid * F_IN + f];
            s += xv * ws[f];
            d += xv * ws[F_IN + f];
        }
        g_es[gt] = s + g_eemb_s[n];
        g_ed[gt] = d + g_eemb_d[n];
    }
}

// ---------------- K3: attention softmax + gather-weighted sum + head -------
__global__ void k3_out(const float* __restrict__ lin_W,
                       const float* __restrict__ lin_b,
                       float* __restrict__ y) {
    int tid = threadIdx.x;           // 128 = 4 warps, 1 token per warp
    int wid = tid >> 5, lane = tid & 31;
    int t = blockIdx.x * 4 + wid;    // global token
    int b = t >> 10;
    int n = t & (N - 1);

    int   i  = g_idx[n * TOPK + lane];
    float ed = g_ed[b * N + i];
    float es = g_es[t];
    float sc = es + ed;
    sc = sc >= 0.f ? sc : NEG_SLOPE * sc;

    float m = sc;
    #pragma unroll
    for (int o = 16; o; o >>= 1) m = fmaxf(m, __shfl_xor_sync(0xffffffffu, m, o));
    float p = expf(sc - m);
    float s = p;
    #pragma unroll
    for (int o = 16; o; o >>= 1) s += __shfl_xor_sync(0xffffffffu, s, o);
    float alpha = p / s;

    const float4* h4 = (const float4*)g_h + (size_t)b * N * (E / 4);
    float4 acc = {0.f, 0.f, 0.f, 0.f};
    #pragma unroll
    for (int k = 0; k < TOPK; k++) {
        float a  = __shfl_sync(0xffffffffu, alpha, k);
        int   ii = __shfl_sync(0xffffffffu, i, k);
        float4 hv = h4[(size_t)ii * (E / 4) + lane];
        acc.x += a * hv.x; acc.y += a * hv.y; acc.z += a * hv.z; acc.w += a * hv.w;
    }
    acc.x = fmaxf(acc.x, 0.f); acc.y = fmaxf(acc.y, 0.f);
    acc.z = fmaxf(acc.z, 0.f); acc.w = fmaxf(acc.w, 0.f);
    float4 lw = ((const float4*)lin_W)[lane];
    float part = acc.x * lw.x + acc.y * lw.y + acc.z * lw.z + acc.w * lw.w;
    #pragma unroll
    for (int o = 16; o; o >>= 1) part += __shfl_xor_sync(0xffffffffu, part, o);
    if (lane == 0) y[t] = part + lin_b[0];
}

// ---------------- launch ---------------------------------------------------
extern "C" void kernel_launch(void* const* d_in, const int* in_sizes, int n_in,
                              void* d_out, int out_size) {
    const float* x     = (const float*)d_in[0];
    const float* emb   = (const float*)d_in[1];
    const float* Wfe   = (const float*)d_in[2];
    const float* a_src = (const float*)d_in[3];
    const float* a_dst = (const float*)d_in[4];
    const float* lin_W = (const float*)d_in[5];
    const float* lin_b = (const float*)d_in[6];
    float* y = (float*)d_out;

    k0_ws<<<1, 128>>>(Wfe, a_src, a_dst);
    k1a_norm<<<N, 128>>>(emb, a_src, a_dst);
    k1b_topk<<<N / ROWS, 256>>>();
    k2_h<<<(B * N) / TOKB, 128>>>(x, Wfe);
    k3_out<<<(B * N) / 4, 128>>>(lin_W, lin_b, y);
}

// round 2
// speedup vs baseline: 1.0367x; 1.0367x over previous
#include <cuda_runtime.h>
#include <cuda_fp16.h>
#include <math.h>

#define B 64
#define N 1024
#define F_IN 64
#define E 128
#define TOPK 32
#define NEG_SLOPE 0.2f

// ---------------- scratch (device globals; no allocation allowed) ----------
__device__ __align__(16) __half g_h[B * N * E];    // 16 MB, fp16 storage
__device__ float g_es[B * N];
__device__ float g_ed[B * N];
__device__ __align__(16) float g_embn[N * E];      // normalized emb
__device__ float g_eemb_s[N];
__device__ float g_eemb_d[N];
__device__ float g_ws[2 * F_IN];                   // [ws_src | ws_dst]
__device__ int   g_idx[N * TOPK];

// ---------------- K0: ws_src[f] = sum_e W_fe[f,e]*a_src[e]  (and dst) ------
__global__ void k0_ws(const float* __restrict__ Wfe,
                      const float* __restrict__ a_src,
                      const float* __restrict__ a_dst) {
    int t = threadIdx.x;  // 128 threads
    if (t < F_IN) {
        float s = 0.f;
        #pragma unroll 8
        for (int e = 0; e < E; e++) s += Wfe[t * E + e] * a_src[e];
        g_ws[t] = s;
    } else {
        int f = t - F_IN;
        float s = 0.f;
        #pragma unroll 8
        for (int e = 0; e < E; e++) s += Wfe[f * E + e] * a_dst[e];
        g_ws[F_IN + f] = s;
    }
}

// ---------------- K1a: normalize emb rows + emb-side attention dots --------
__global__ void k1a_norm(const float* __restrict__ emb,
                         const float* __restrict__ a_src,
                         const float* __restrict__ a_dst) {
    int n = blockIdx.x;
    int e = threadIdx.x;  // 128
    int lane = e & 31, wid = e >> 5;
    __shared__ float sm[12];
    float v  = emb[n * E + e];
    float r0 = v * v;
    float r1 = v * a_src[E + e];
    float r2 = v * a_dst[E + e];
    #pragma unroll
    for (int o = 16; o; o >>= 1) {
        r0 += __shfl_xor_sync(0xffffffffu, r0, o);
        r1 += __shfl_xor_sync(0xffffffffu, r1, o);
        r2 += __shfl_xor_sync(0xffffffffu, r2, o);
    }
    if (lane == 0) { sm[wid] = r0; sm[4 + wid] = r1; sm[8 + wid] = r2; }
    __syncthreads();
    float sumsq = sm[0] + sm[1] + sm[2] + sm[3];
    g_embn[n * E + e] = v * rsqrtf(sumsq);
    if (e == 0) {
        g_eemb_s[n] = sm[4] + sm[5] + sm[6] + sm[7];
        g_eemb_d[n] = sm[8] + sm[9] + sm[10] + sm[11];
    }
}

// ---------------- K1b: cosine sim rows + top-32 (set semantics) ------------
#define ROWS 8
__global__ void k1b_topk() {
    __shared__ __align__(16) float q[ROWS * E];     // 4 KB
    __shared__ float sims[ROWS][N];                 // 32 KB
    int tid = threadIdx.x;                           // 256
    int row0 = blockIdx.x * ROWS;

    for (int i = tid; i < ROWS * E; i += 256) q[i] = g_embn[row0 * E + i];
    __syncthreads();

    const float4* q4 = (const float4*)q;
    const float4* g4 = (const float4*)g_embn;

    for (int c = tid; c < N; c += 256) {
        float acc[ROWS];
        #pragma unroll
        for (int r = 0; r < ROWS; r++) acc[r] = 0.f;
        const float4* rp = g4 + (size_t)c * (E / 4);
        #pragma unroll 4
        for (int j = 0; j < E / 4; j++) {
            float4 rv = rp[j];
            #pragma unroll
            for (int r = 0; r < ROWS; r++) {
                float4 qv = q4[r * (E / 4) + j];
                acc[r] += rv.x * qv.x + rv.y * qv.y + rv.z * qv.z + rv.w * qv.w;
            }
        }
        #pragma unroll
        for (int r = 0; r < ROWS; r++) sims[r][c] = acc[r];
    }
    __syncthreads();

    int wid = tid >> 5, lane = tid & 31;
    if (wid < ROWS) {
        int r = wid;
        for (int round = 0; round < TOPK; round++) {
            float bv = -INFINITY; int bi = N;
            for (int c = lane; c < N; c += 32) {
                float v = sims[r][c];
                if (v > bv || (v == bv && c < bi)) { bv = v; bi = c; }
            }
            #pragma unroll
            for (int o = 16; o; o >>= 1) {
                float ov = __shfl_xor_sync(0xffffffffu, bv, o);
                int   oi = __shfl_xor_sync(0xffffffffu, bi, o);
                if (ov > bv || (ov == bv && oi < bi)) { bv = ov; bi = oi; }
            }
            if (lane == 0) {
                g_idx[(row0 + r) * TOPK + round] = bi;
                sims[r][bi] = -INFINITY;
            }
            __syncwarp();
        }
    }
}

// ---------------- K2: h = x @ W_fe (fp16 out); e_s/e_d per token -----------
// 128 threads; 32 tokens/block; per thread: 4 tokens x 8 e-columns.
#define TOKB 32
__global__ void k2_h(const float* __restrict__ x,
                     const float* __restrict__ Wfe) {
    __shared__ __align__(16) float Ws[F_IN * E];     // 32 KB
    __shared__ __align__(16) float xs[TOKB * F_IN];  // 8 KB
    __shared__ float ws[2 * F_IN];
    int tid = threadIdx.x;  // 128
    int t0 = blockIdx.x * TOKB;

    {   // cooperative loads
        float4* Wd = (float4*)Ws;
        const float4* Wsrc = (const float4*)Wfe;
        #pragma unroll
        for (int i = 0; i < (F_IN * E / 4) / 128; i++)
            Wd[tid + i * 128] = Wsrc[tid + i * 128];
        float4* xd = (float4*)xs;
        const float4* xsrc = (const float4*)(x + (size_t)t0 * F_IN);
        #pragma unroll
        for (int i = 0; i < (TOKB * F_IN / 4) / 128; i++)
            xd[tid + i * 128] = xsrc[tid + i * 128];
        ws[tid] = g_ws[tid];
    }
    __syncthreads();

    int eg = tid & 15;   // e-group: e in [eg*8, eg*8+8)
    int tg = tid >> 4;   // token group: tokens tg*4 .. tg*4+3
    const float4* W4 = (const float4*)Ws;

    float4 a0l = {0,0,0,0}, a0h = {0,0,0,0};
    float4 a1l = {0,0,0,0}, a1h = {0,0,0,0};
    float4 a2l = {0,0,0,0}, a2h = {0,0,0,0};
    float4 a3l = {0,0,0,0}, a3h = {0,0,0,0};
    #pragma unroll 4
    for (int f = 0; f < F_IN; f++) {
        float4 w0 = W4[f * 32 + eg * 2 + 0];
        float4 w1 = W4[f * 32 + eg * 2 + 1];
        float x0 = xs[(tg * 4 + 0) * F_IN + f];
        float x1 = xs[(tg * 4 + 1) * F_IN + f];
        float x2 = xs[(tg * 4 + 2) * F_IN + f];
        float x3 = xs[(tg * 4 + 3) * F_IN + f];
        a0l.x += x0*w0.x; a0l.y += x0*w0.y; a0l.z += x0*w0.z; a0l.w += x0*w0.w;
        a0h.x += x0*w1.x; a0h.y += x0*w1.y; a0h.z += x0*w1.z; a0h.w += x0*w1.w;
        a1l.x += x1*w0.x; a1l.y += x1*w0.y; a1l.z += x1*w0.z; a1l.w += x1*w0.w;
        a1h.x += x1*w1.x; a1h.y += x1*w1.y; a1h.z += x1*w1.z; a1h.w += x1*w1.w;
        a2l.x += x2*w0.x; a2l.y += x2*w0.y; a2l.z += x2*w0.z; a2l.w += x2*w0.w;
        a2h.x += x2*w1.x; a2h.y += x2*w1.y; a2h.z += x2*w1.z; a2h.w += x2*w1.w;
        a3l.x += x3*w0.x; a3l.y += x3*w0.y; a3l.z += x3*w0.z; a3l.w += x3*w0.w;
        a3h.x += x3*w1.x; a3h.y += x3*w1.y; a3h.z += x3*w1.z; a3h.w += x3*w1.w;
    }

    // store fp16: 8 halves = 16B per token per thread
    {
        uint4* hdst = (uint4*)g_h;   // 16B granules; E halves per row = 8 granules
        size_t base = (size_t)(t0 + tg * 4) * (E / 8) + eg;
        uint4 v;
        __half2* vh = (__half2*)&v;
        vh[0] = __floats2half2_rn(a0l.x, a0l.y); vh[1] = __floats2half2_rn(a0l.z, a0l.w);
        vh[2] = __floats2half2_rn(a0h.x, a0h.y); vh[3] = __floats2half2_rn(a0h.z, a0h.w);
        hdst[base + 0 * (E / 8)] = v;
        vh[0] = __floats2half2_rn(a1l.x, a1l.y); vh[1] = __floats2half2_rn(a1l.z, a1l.w);
        vh[2] = __floats2half2_rn(a1h.x, a1h.y); vh[3] = __floats2half2_rn(a1h.z, a1h.w);
        hdst[base + 1 * (E / 8)] = v;
        vh[0] = __floats2half2_rn(a2l.x, a2l.y); vh[1] = __floats2half2_rn(a2l.z, a2l.w);
        vh[2] = __floats2half2_rn(a2h.x, a2h.y); vh[3] = __floats2half2_rn(a2h.z, a2h.w);
        hdst[base + 2 * (E / 8)] = v;
        vh[0] = __floats2half2_rn(a3l.x, a3l.y); vh[1] = __floats2half2_rn(a3l.z, a3l.w);
        vh[2] = __floats2half2_rn(a3h.x, a3h.y); vh[3] = __floats2half2_rn(a3h.z, a3h.w);
        hdst[base + 3 * (E / 8)] = v;
    }

    // e_s / e_d for the block's 32 tokens
    if (tid < TOKB) {
        int gt = t0 + tid;
        int n = gt & (N - 1);
        float s = 0.f, d = 0.f;
        #pragma unroll 8
        for (int f = 0; f < F_IN; f++) {
            float xv = xs[tid * F_IN + f];
            s += xv * ws[f];
            d += xv * ws[F_IN + f];
        }
        g_es[gt] = s + g_eemb_s[n];
        g_ed[gt] = d + g_eemb_d[n];
    }
}

// ---------------- K3: attention softmax + gather-weighted sum + head -------
__global__ void k3_out(const float* __restrict__ lin_W,
                       const float* __restrict__ lin_b,
                       float* __restrict__ y) {
    int tid = threadIdx.x;           // 128 = 4 warps, 1 token per warp
    int wid = tid >> 5, lane = tid & 31;
    int t = blockIdx.x * 4 + wid;    // global token
    int b = t >> 10;
    int n = t & (N - 1);

    int   i  = g_idx[n * TOPK + lane];
    float ed = g_ed[b * N + i];
    float es = g_es[t];
    float sc = es + ed;
    sc = sc >= 0.f ? sc : NEG_SLOPE * sc;

    float m = sc;
    #pragma unroll
    for (int o = 16; o; o >>= 1) m = fmaxf(m, __shfl_xor_sync(0xffffffffu, m, o));
    float p = __expf(sc - m);
    float s = p;
    #pragma unroll
    for (int o = 16; o; o >>= 1) s += __shfl_xor_sync(0xffffffffu, s, o);
    float alpha = p / s;

    // lane covers e in [lane*4, lane*4+4): 4 halves = 8 bytes per row
    const __half* hb = g_h + (size_t)b * N * E;
    float4 acc = {0.f, 0.f, 0.f, 0.f};
    #pragma unroll
    for (int k = 0; k < TOPK; k++) {
        float a  = __shfl_sync(0xffffffffu, alpha, k);
        int   ii = __shfl_sync(0xffffffffu, i, k);
        uint2 raw = *(const uint2*)(hb + (size_t)ii * E + lane * 4);
        __half2 h01 = *(__half2*)&raw.x;
        __half2 h23 = *(__half2*)&raw.y;
        float2 f01 = __half22float2(h01);
        float2 f23 = __half22float2(h23);
        acc.x += a * f01.x; acc.y += a * f01.y;
        acc.z += a * f23.x; acc.w += a * f23.y;
    }
    acc.x = fmaxf(acc.x, 0.f); acc.y = fmaxf(acc.y, 0.f);
    acc.z = fmaxf(acc.z, 0.f); acc.w = fmaxf(acc.w, 0.f);
    float4 lw = ((const float4*)lin_W)[lane];
    float part = acc.x * lw.x + acc.y * lw.y + acc.z * lw.z + acc.w * lw.w;
    #pragma unroll
    for (int o = 16; o; o >>= 1) part += __shfl_xor_sync(0xffffffffu, part, o);
    if (lane == 0) y[t] = part + lin_b[0];
}

// ---------------- launch ---------------------------------------------------
extern "C" void kernel_launch(void* const* d_in, const int* in_sizes, int n_in,
                              void* d_out, int out_size) {
    const float* x     = (const float*)d_in[0];
    const float* emb   = (const float*)d_in[1];
    const float* Wfe   = (const float*)d_in[2];
    const float* a_src = (const float*)d_in[3];
    const float* a_dst = (const float*)d_in[4];
    const float* lin_W = (const float*)d_in[5];
    const float* lin_b = (const float*)d_in[6];
    float* y = (float*)d_out;

    k0_ws<<<1, 128>>>(Wfe, a_src, a_dst);
    k1a_norm<<<N, 128>>>(emb, a_src, a_dst);
    k1b_topk<<<N / ROWS, 256>>>();
    k2_h<<<(B * N) / TOKB, 128>>>(x, Wfe);
    k3_out<<<(B * N) / 4, 128>>>(lin_W, lin_b, y);
}

// round 3
// speedup vs baseline: 1.2033x; 1.1607x over previous
#include <cuda_runtime.h>
#include <cuda_fp16.h>
#include <math.h>

#define B 64
#define N 1024
#define F_IN 64
#define E 128
#define TOPK 32
#define NEG_SLOPE 0.2f

// ---------------- scratch (device globals; no allocation allowed) ----------
__device__ __align__(16) __half g_h[B * N * E];    // 16 MB, fp16 storage
__device__ float g_es[B * N];
__device__ float g_ed[B * N];
__device__ __align__(16) float g_embn[N * E];      // normalized emb
__device__ float g_eemb_s[N];
__device__ float g_eemb_d[N];
__device__ float g_ws[2 * F_IN];                   // [ws_src | ws_dst]
__device__ int   g_idx[N * TOPK];

// ---------------- K0: ws_src[f] = sum_e W_fe[f,e]*a_src[e]  (and dst) ------
__global__ void k0_ws(const float* __restrict__ Wfe,
                      const float* __restrict__ a_src,
                      const float* __restrict__ a_dst) {
    int t = threadIdx.x;  // 128 threads
    if (t < F_IN) {
        float s = 0.f;
        #pragma unroll 8
        for (int e = 0; e < E; e++) s += Wfe[t * E + e] * a_src[e];
        g_ws[t] = s;
    } else {
        int f = t - F_IN;
        float s = 0.f;
        #pragma unroll 8
        for (int e = 0; e < E; e++) s += Wfe[f * E + e] * a_dst[e];
        g_ws[F_IN + f] = s;
    }
}

// ---------------- K1a: normalize emb rows + emb-side attention dots --------
__global__ void k1a_norm(const float* __restrict__ emb,
                         const float* __restrict__ a_src,
                         const float* __restrict__ a_dst) {
    int n = blockIdx.x;
    int e = threadIdx.x;  // 128
    int lane = e & 31, wid = e >> 5;
    __shared__ float sm[12];
    float v  = emb[n * E + e];
    float r0 = v * v;
    float r1 = v * a_src[E + e];
    float r2 = v * a_dst[E + e];
    #pragma unroll
    for (int o = 16; o; o >>= 1) {
        r0 += __shfl_xor_sync(0xffffffffu, r0, o);
        r1 += __shfl_xor_sync(0xffffffffu, r1, o);
        r2 += __shfl_xor_sync(0xffffffffu, r2, o);
    }
    if (lane == 0) { sm[wid] = r0; sm[4 + wid] = r1; sm[8 + wid] = r2; }
    __syncthreads();
    float sumsq = sm[0] + sm[1] + sm[2] + sm[3];
    g_embn[n * E + e] = v * rsqrtf(sumsq);
    if (e == 0) {
        g_eemb_s[n] = sm[4] + sm[5] + sm[6] + sm[7];
        g_eemb_d[n] = sm[8] + sm[9] + sm[10] + sm[11];
    }
}

// ---------------- K1b: cosine sim rows + top-32 (set semantics) ------------
#define ROWS 8
__global__ void k1b_topk() {
    __shared__ __align__(16) float q[ROWS * E];     // 4 KB
    __shared__ float sims[ROWS][N];                 // 32 KB
    int tid = threadIdx.x;                           // 256
    int row0 = blockIdx.x * ROWS;

    for (int i = tid; i < ROWS * E; i += 256) q[i] = g_embn[row0 * E + i];
    __syncthreads();

    const float4* q4 = (const float4*)q;
    const float4* g4 = (const float4*)g_embn;

    for (int c = tid; c < N; c += 256) {
        float acc[ROWS];
        #pragma unroll
        for (int r = 0; r < ROWS; r++) acc[r] = 0.f;
        const float4* rp = g4 + (size_t)c * (E / 4);
        #pragma unroll 4
        for (int j = 0; j < E / 4; j++) {
            float4 rv = rp[j];
            #pragma unroll
            for (int r = 0; r < ROWS; r++) {
                float4 qv = q4[r * (E / 4) + j];
                acc[r] += rv.x * qv.x + rv.y * qv.y + rv.z * qv.z + rv.w * qv.w;
            }
        }
        #pragma unroll
        for (int r = 0; r < ROWS; r++) sims[r][c] = acc[r];
    }
    __syncthreads();

    int wid = tid >> 5, lane = tid & 31;
    if (wid < ROWS) {
        int r = wid;
        for (int round = 0; round < TOPK; round++) {
            float bv = -INFINITY; int bi = N;
            for (int c = lane; c < N; c += 32) {
                float v = sims[r][c];
                if (v > bv || (v == bv && c < bi)) { bv = v; bi = c; }
            }
            #pragma unroll
            for (int o = 16; o; o >>= 1) {
                float ov = __shfl_xor_sync(0xffffffffu, bv, o);
                int   oi = __shfl_xor_sync(0xffffffffu, bi, o);
                if (ov > bv || (ov == bv && oi < bi)) { bv = ov; bi = oi; }
            }
            if (lane == 0) {
                g_idx[(row0 + r) * TOPK + round] = bi;
                sims[r][bi] = -INFINITY;
            }
            __syncwarp();
        }
    }
}

// ---------------- K_esd: e_s / e_d per token (warp per token) --------------
__global__ void k_esd(const float* __restrict__ x) {
    int warp = (blockIdx.x * blockDim.x + threadIdx.x) >> 5;  // token id
    int lane = threadIdx.x & 31;
    const float2* xr = (const float2*)(x + (size_t)warp * F_IN);
    float2 v = xr[lane];                       // covers f = lane*2, lane*2+1
    float s = v.x * g_ws[lane * 2] + v.y * g_ws[lane * 2 + 1];
    float d = v.x * g_ws[F_IN + lane * 2] + v.y * g_ws[F_IN + lane * 2 + 1];
    #pragma unroll
    for (int o = 16; o; o >>= 1) {
        s += __shfl_xor_sync(0xffffffffu, s, o);
        d += __shfl_xor_sync(0xffffffffu, d, o);
    }
    if (lane == 0) {
        int n = warp & (N - 1);
        g_es[warp] = s + g_eemb_s[n];
        g_ed[warp] = d + g_eemb_d[n];
    }
}

// ---------------- K2: h = x @ W_fe via tensor cores (fp16 in/out) ----------
// block: 256 thr = 8 warps (4 m x 2 n); tile 128 tokens x 128 E; K = 64.
#define XS_STRIDE 72      // halves, padded
#define CS_STRIDE 136     // halves, padded

__device__ __forceinline__ void mma16816(float* c, const unsigned* a, const unsigned* b) {
    asm volatile(
        "mma.sync.aligned.m16n8k16.row.col.f32.f16.f16.f32 "
        "{%0,%1,%2,%3}, {%4,%5,%6,%7}, {%8,%9}, {%0,%1,%2,%3};\n"
        : "+f"(c[0]), "+f"(c[1]), "+f"(c[2]), "+f"(c[3])
        : "r"(a[0]), "r"(a[1]), "r"(a[2]), "r"(a[3]), "r"(b[0]), "r"(b[1]));
}

__global__ void __launch_bounds__(256) k2_tc(const float* __restrict__ x,
                                             const float* __restrict__ Wfe) {
    __shared__ __align__(16) char sbuf[2 * 128 * XS_STRIDE * 2];  // 36864 B
    __half* xs = (__half*)sbuf;                        // [128][72]
    __half* Ws = (__half*)(sbuf + 128 * XS_STRIDE * 2); // [128 e][72 f] = W^T
    int tid = threadIdx.x;
    int t0 = blockIdx.x * 128;

    // load & convert x tile (128x64 fp32 -> fp16)
    {
        const float4* xsrc = (const float4*)(x + (size_t)t0 * F_IN);
        #pragma unroll
        for (int it = 0; it < 8; it++) {
            int idx = tid + it * 256;     // 0..2047 float4
            int row = idx >> 4;
            int c4  = idx & 15;
            float4 v = xsrc[idx];
            __half2* dst = (__half2*)(xs + row * XS_STRIDE + c4 * 4);
            dst[0] = __floats2half2_rn(v.x, v.y);
            dst[1] = __floats2half2_rn(v.z, v.w);
        }
        // W transpose: Wfe[f][e] -> Ws[e][f]
        const float4* wsrc = (const float4*)Wfe;   // 64 x 32 float4
        #pragma unroll
        for (int it = 0; it < 8; it++) {
            int idx = tid + it * 256;     // 0..2047
            int f  = idx >> 5;
            int e4 = idx & 31;
            float4 v = wsrc[idx];
            Ws[(e4 * 4 + 0) * XS_STRIDE + f] = __float2half_rn(v.x);
            Ws[(e4 * 4 + 1) * XS_STRIDE + f] = __float2half_rn(v.y);
            Ws[(e4 * 4 + 2) * XS_STRIDE + f] = __float2half_rn(v.z);
            Ws[(e4 * 4 + 3) * XS_STRIDE + f] = __float2half_rn(v.w);
        }
    }
    __syncthreads();

    int lane = tid & 31, warp = tid >> 5;
    int wm = warp & 3, wn = warp >> 2;       // m off = wm*32, n off = wn*64
    int gid = lane >> 2, qid = lane & 3;

    float c[2][8][4];
    #pragma unroll
    for (int mi = 0; mi < 2; mi++)
        #pragma unroll
        for (int ni = 0; ni < 8; ni++)
            #pragma unroll
            for (int q = 0; q < 4; q++) c[mi][ni][q] = 0.f;

    #pragma unroll
    for (int kk = 0; kk < F_IN; kk += 16) {
        unsigned a[2][4];
        #pragma unroll
        for (int mi = 0; mi < 2; mi++) {
            int r = wm * 32 + mi * 16 + gid;
            int cb = qid * 2 + kk;
            a[mi][0] = *(unsigned*)(xs + r * XS_STRIDE + cb);
            a[mi][1] = *(unsigned*)(xs + (r + 8) * XS_STRIDE + cb);
            a[mi][2] = *(unsigned*)(xs + r * XS_STRIDE + cb + 8);
            a[mi][3] = *(unsigned*)(xs + (r + 8) * XS_STRIDE + cb + 8);
        }
        #pragma unroll
        for (int ni = 0; ni < 8; ni++) {
            int col = wn * 64 + ni * 8 + gid;
            int rb = qid * 2 + kk;
            unsigned bb[2];
            bb[0] = *(unsigned*)(Ws + col * XS_STRIDE + rb);
            bb[1] = *(unsigned*)(Ws + col * XS_STRIDE + rb + 8);
            mma16816(c[0][ni], a[0], bb);
            mma16816(c[1][ni], a[1], bb);
        }
    }
    __syncthreads();  // everyone done reading xs/Ws

    // stage C tile in smem fp16 for coalesced global store
    __half* cs = (__half*)sbuf;   // [128][136]
    #pragma unroll
    for (int mi = 0; mi < 2; mi++)
        #pragma unroll
        for (int ni = 0; ni < 8; ni++) {
            int r = wm * 32 + mi * 16 + gid;
            int e = wn * 64 + ni * 8 + qid * 2;
            *(__half2*)(cs + r * CS_STRIDE + e) =
                __floats2half2_rn(c[mi][ni][0], c[mi][ni][1]);
            *(__half2*)(cs + (r + 8) * CS_STRIDE + e) =
                __floats2half2_rn(c[mi][ni][2], c[mi][ni][3]);
        }
    __syncthreads();

    uint4* dst = (uint4*)(g_h + (size_t)t0 * E);
    #pragma unroll
    for (int it = 0; it < 8; it++) {
        int idx = tid + it * 256;   // 0..2047 uint4; 16 per row
        int row = idx >> 4;
        int c8  = idx & 15;
        dst[idx] = *(uint4*)(cs + row * CS_STRIDE + c8 * 8);
    }
}

// ---------------- K3: attention softmax + gather-weighted sum + head -------
// 256 thr = 8 warps, 1 token per warp; 2 neighbor rows per iter (LDG.128).
__global__ void __launch_bounds__(256) k3_out(const float* __restrict__ lin_W,
                                              const float* __restrict__ lin_b,
                                              float* __restrict__ y) {
    int tid = threadIdx.x;
    int wid = tid >> 5, lane = tid & 31;
    int t = blockIdx.x * 8 + wid;
    int b = t >> 10;
    int n = t & (N - 1);

    int   i  = g_idx[n * TOPK + lane];      // lane = k
    float ed = g_ed[(b << 10) + i];
    float es = g_es[t];
    float sc = es + ed;
    sc = sc >= 0.f ? sc : NEG_SLOPE * sc;

    float m = sc;
    #pragma unroll
    for (int o = 16; o; o >>= 1) m = fmaxf(m, __shfl_xor_sync(0xffffffffu, m, o));
    float p = __expf(sc - m);
    float s = p;
    #pragma unroll
    for (int o = 16; o; o >>= 1) s += __shfl_xor_sync(0xffffffffu, s, o);
    float alpha = p / s;

    const __half* hb = g_h + ((size_t)b << 10) * E;
    int hw = lane >> 4, sl = lane & 15;     // half-warp id, slice id (e = sl*8..+8)
    float acc[8];
    #pragma unroll
    for (int q = 0; q < 8; q++) acc[q] = 0.f;

    #pragma unroll
    for (int j = 0; j < 16; j++) {
        int kk = j * 2 + hw;
        float a  = __shfl_sync(0xffffffffu, alpha, kk);
        int   ii = __shfl_sync(0xffffffffu, i, kk);
        uint4 raw = *(const uint4*)(hb + (size_t)ii * E + sl * 8);
        __half2* hp = (__half2*)&raw;
        #pragma unroll
        for (int q = 0; q < 4; q++) {
            float2 f = __half22float2(hp[q]);
            acc[q * 2]     += a * f.x;
            acc[q * 2 + 1] += a * f.y;
        }
    }
    // combine even-k / odd-k halves
    #pragma unroll
    for (int q = 0; q < 8; q++) acc[q] += __shfl_xor_sync(0xffffffffu, acc[q], 16);

    const float4* lw4 = (const float4*)lin_W;
    float4 l0 = lw4[sl * 2], l1 = lw4[sl * 2 + 1];
    float part = fmaxf(acc[0], 0.f) * l0.x + fmaxf(acc[1], 0.f) * l0.y
               + fmaxf(acc[2], 0.f) * l0.z + fmaxf(acc[3], 0.f) * l0.w
               + fmaxf(acc[4], 0.f) * l1.x + fmaxf(acc[5], 0.f) * l1.y
               + fmaxf(acc[6], 0.f) * l1.z + fmaxf(acc[7], 0.f) * l1.w;
    #pragma unroll
    for (int o = 8; o; o >>= 1) part += __shfl_xor_sync(0xffffffffu, part, o);
    if (lane == 0) y[t] = part + lin_b[0];
}

// ---------------- launch ---------------------------------------------------
extern "C" void kernel_launch(void* const* d_in, const int* in_sizes, int n_in,
                              void* d_out, int out_size) {
    const float* x     = (const float*)d_in[0];
    const float* emb   = (const float*)d_in[1];
    const float* Wfe   = (const float*)d_in[2];
    const float* a_src = (const float*)d_in[3];
    const float* a_dst = (const float*)d_in[4];
    const float* lin_W = (const float*)d_in[5];
    const float* lin_b = (const float*)d_in[6];
    float* y = (float*)d_out;

    k0_ws<<<1, 128>>>(Wfe, a_src, a_dst);
    k1a_norm<<<N, 128>>>(emb, a_src, a_dst);
    k1b_topk<<<N / ROWS, 256>>>();
    k_esd<<<(B * N) / 8, 256>>>(x);
    k2_tc<<<(B * N) / 128, 256>>>(x, Wfe);
    k3_out<<<(B * N) / 8, 256>>>(lin_W, lin_b, y);
}

// round 4
// speedup vs baseline: 1.4054x; 1.1679x over previous
#include <cuda_runtime.h>
#include <cuda_fp16.h>
#include <math.h>

#define B 64
#define N 1024
#define F_IN 64
#define E 128
#define TOPK 32
#define NEG_SLOPE 0.2f

// ---------------- scratch (device globals; no allocation allowed) ----------
__device__ __align__(16) __half g_h[B * N * E];    // 16 MB, fp16 storage
__device__ float g_es[B * N];
__device__ float g_ed[B * N];
__device__ __align__(16) float g_embn[N * E];      // normalized emb
__device__ float g_eemb_s[N];
__device__ float g_eemb_d[N];
__device__ __align__(16) float g_ws[2 * F_IN];     // [ws_src | ws_dst]
__device__ int   g_idx[N * TOPK];

// ---------------- K0: ws_src[f] = sum_e W_fe[f,e]*a_src[e]  (and dst) ------
__global__ void k0_ws(const float* __restrict__ Wfe,
                      const float* __restrict__ a_src,
                      const float* __restrict__ a_dst) {
    int t = threadIdx.x;  // 128 threads
    if (t < F_IN) {
        float s = 0.f;
        #pragma unroll 8
        for (int e = 0; e < E; e++) s += Wfe[t * E + e] * a_src[e];
        g_ws[t] = s;
    } else {
        int f = t - F_IN;
        float s = 0.f;
        #pragma unroll 8
        for (int e = 0; e < E; e++) s += Wfe[f * E + e] * a_dst[e];
        g_ws[F_IN + f] = s;
    }
}

// ---------------- K1a: normalize emb rows + emb-side attention dots --------
__global__ void k1a_norm(const float* __restrict__ emb,
                         const float* __restrict__ a_src,
                         const float* __restrict__ a_dst) {
    int n = blockIdx.x;
    int e = threadIdx.x;  // 128
    int lane = e & 31, wid = e >> 5;
    __shared__ float sm[12];
    float v  = emb[n * E + e];
    float r0 = v * v;
    float r1 = v * a_src[E + e];
    float r2 = v * a_dst[E + e];
    #pragma unroll
    for (int o = 16; o; o >>= 1) {
        r0 += __shfl_xor_sync(0xffffffffu, r0, o);
        r1 += __shfl_xor_sync(0xffffffffu, r1, o);
        r2 += __shfl_xor_sync(0xffffffffu, r2, o);
    }
    if (lane == 0) { sm[wid] = r0; sm[4 + wid] = r1; sm[8 + wid] = r2; }
    __syncthreads();
    float sumsq = sm[0] + sm[1] + sm[2] + sm[3];
    g_embn[n * E + e] = v * rsqrtf(sumsq);
    if (e == 0) {
        g_eemb_s[n] = sm[4] + sm[5] + sm[6] + sm[7];
        g_eemb_d[n] = sm[8] + sm[9] + sm[10] + sm[11];
    }
}

// ---------------- K1b: cosine sim rows + top-32 (set semantics) ------------
#define ROWS 8
__global__ void __launch_bounds__(256) k1b_topk() {
    __shared__ __align__(16) float q[ROWS * E];     // 4 KB
    __shared__ float sims[ROWS][N];                 // 32 KB
    int tid = threadIdx.x;                           // 256
    int row0 = blockIdx.x * ROWS;

    for (int i = tid; i < ROWS * E; i += 256) q[i] = g_embn[row0 * E + i];
    __syncthreads();

    const float4* q4 = (const float4*)q;
    const float4* g4 = (const float4*)g_embn;

    for (int c = tid; c < N; c += 256) {
        float acc[ROWS];
        #pragma unroll
        for (int r = 0; r < ROWS; r++) acc[r] = 0.f;
        const float4* rp = g4 + (size_t)c * (E / 4);
        #pragma unroll 4
        for (int j = 0; j < E / 4; j++) {
            float4 rv = rp[j];
            #pragma unroll
            for (int r = 0; r < ROWS; r++) {
                float4 qv = q4[r * (E / 4) + j];
                acc[r] += rv.x * qv.x + rv.y * qv.y + rv.z * qv.z + rv.w * qv.w;
            }
        }
        #pragma unroll
        for (int r = 0; r < ROWS; r++) sims[r][c] = acc[r];
    }
    __syncthreads();

    // selection: warp r owns row r; lane caches its 32 columns in registers
    int wid = tid >> 5, lane = tid & 31;
    int r = wid;
    float vals[32];
    #pragma unroll
    for (int j = 0; j < 32; j++) vals[j] = sims[r][j * 32 + lane];

    // local best (ascending j scan with strict > keeps lowest index on ties)
    float bv = vals[0]; int bj = 0;
    #pragma unroll
    for (int j = 1; j < 32; j++)
        if (vals[j] > bv) { bv = vals[j]; bj = j; }

    for (int round = 0; round < TOPK; round++) {
        float wv = bv;
        int   wi = bj * 32 + lane;   // global column
        #pragma unroll
        for (int o = 16; o; o >>= 1) {
            float ov = __shfl_xor_sync(0xffffffffu, wv, o);
            int   oi = __shfl_xor_sync(0xffffffffu, wi, o);
            if (ov > wv || (ov == wv && oi < wi)) { wv = ov; wi = oi; }
        }
        if (lane == 0) g_idx[(row0 + r) * TOPK + round] = wi;
        // winner lane invalidates its slot and recomputes local best
        if (lane == (wi & 31)) {
            int jw = wi >> 5;
            #pragma unroll
            for (int j = 0; j < 32; j++) if (j == jw) vals[j] = -INFINITY;
            bv = vals[0]; bj = 0;
            #pragma unroll
            for (int j = 1; j < 32; j++)
                if (vals[j] > bv) { bv = vals[j]; bj = j; }
        }
        __syncwarp();
    }
}

// ---------------- K2: h = x @ W_fe via tensor cores; fused e_s/e_d ---------
// block: 256 thr = 8 warps (4 m x 2 n); tile 128 tokens x 128 E; K = 64.
#define XS_STRIDE 72      // halves, padded
#define CS_STRIDE 136     // halves, padded

__device__ __forceinline__ void mma16816(float* c, const unsigned* a, const unsigned* b) {
    asm volatile(
        "mma.sync.aligned.m16n8k16.row.col.f32.f16.f16.f32 "
        "{%0,%1,%2,%3}, {%4,%5,%6,%7}, {%8,%9}, {%0,%1,%2,%3};\n"
        : "+f"(c[0]), "+f"(c[1]), "+f"(c[2]), "+f"(c[3])
        : "r"(a[0]), "r"(a[1]), "r"(a[2]), "r"(a[3]), "r"(b[0]), "r"(b[1]));
}

__global__ void __launch_bounds__(256) k2_tc(const float* __restrict__ x,
                                             const float* __restrict__ Wfe) {
    __shared__ __align__(16) char sbuf[2 * 128 * XS_STRIDE * 2];  // 36864 B
    __half* xs = (__half*)sbuf;                        // [128][72]
    __half* Ws = (__half*)(sbuf + 128 * XS_STRIDE * 2); // [128 e][72 f] = W^T
    int tid = threadIdx.x;
    int t0 = blockIdx.x * 128;

    // load & convert x tile (128x64 fp32 -> fp16) + fused e_s/e_d
    {
        const float4* xsrc = (const float4*)(x + (size_t)t0 * F_IN);
        const float4* ws4  = (const float4*)g_ws;
        int c4 = tid & 15;
        float4 wsv = __ldg(ws4 + c4);        // ws_src[f4]
        float4 wdv = __ldg(ws4 + 16 + c4);   // ws_dst[f4]
        #pragma unroll
        for (int it = 0; it < 8; it++) {
            int idx = tid + it * 256;     // 0..2047 float4
            int row = idx >> 4;
            float4 v = xsrc[idx];
            __half2* dst = (__half2*)(xs + row * XS_STRIDE + c4 * 4);
            dst[0] = __floats2half2_rn(v.x, v.y);
            dst[1] = __floats2half2_rn(v.z, v.w);
            // partial e_s/e_d for this row's 4 features
            float s = v.x * wsv.x + v.y * wsv.y + v.z * wsv.z + v.w * wsv.w;
            float d = v.x * wdv.x + v.y * wdv.y + v.z * wdv.z + v.w * wdv.w;
            #pragma unroll
            for (int o = 8; o; o >>= 1) {
                s += __shfl_xor_sync(0xffffffffu, s, o);
                d += __shfl_xor_sync(0xffffffffu, d, o);
            }
            if (c4 == 0) {
                int gt = t0 + row;
                int n = gt & (N - 1);
                g_es[gt] = s + __ldg(&g_eemb_s[n]);
                g_ed[gt] = d + __ldg(&g_eemb_d[n]);
            }
        }
        // W transpose: Wfe[f][e] -> Ws[e][f]
        const float4* wsrc = (const float4*)Wfe;   // 64 x 32 float4
        #pragma unroll
        for (int it = 0; it < 8; it++) {
            int idx = tid + it * 256;     // 0..2047
            int f  = idx >> 5;
            int e4 = idx & 31;
            float4 v = wsrc[idx];
            Ws[(e4 * 4 + 0) * XS_STRIDE + f] = __float2half_rn(v.x);
            Ws[(e4 * 4 + 1) * XS_STRIDE + f] = __float2half_rn(v.y);
            Ws[(e4 * 4 + 2) * XS_STRIDE + f] = __float2half_rn(v.z);
            Ws[(e4 * 4 + 3) * XS_STRIDE + f] = __float2half_rn(v.w);
        }
    }
    __syncthreads();

    int lane = tid & 31, warp = tid >> 5;
    int wm = warp & 3, wn = warp >> 2;       // m off = wm*32, n off = wn*64
    int gid = lane >> 2, qid = lane & 3;

    float c[2][8][4];
    #pragma unroll
    for (int mi = 0; mi < 2; mi++)
        #pragma unroll
        for (int ni = 0; ni < 8; ni++)
            #pragma unroll
            for (int q = 0; q < 4; q++) c[mi][ni][q] = 0.f;

    #pragma unroll
    for (int kk = 0; kk < F_IN; kk += 16) {
        unsigned a[2][4];
        #pragma unroll
        for (int mi = 0; mi < 2; mi++) {
            int r = wm * 32 + mi * 16 + gid;
            int cb = qid * 2 + kk;
            a[mi][0] = *(unsigned*)(xs + r * XS_STRIDE + cb);
            a[mi][1] = *(unsigned*)(xs + (r + 8) * XS_STRIDE + cb);
            a[mi][2] = *(unsigned*)(xs + r * XS_STRIDE + cb + 8);
            a[mi][3] = *(unsigned*)(xs + (r + 8) * XS_STRIDE + cb + 8);
        }
        #pragma unroll
        for (int ni = 0; ni < 8; ni++) {
            int col = wn * 64 + ni * 8 + gid;
            int rb = qid * 2 + kk;
            unsigned bb[2];
            bb[0] = *(unsigned*)(Ws + col * XS_STRIDE + rb);
            bb[1] = *(unsigned*)(Ws + col * XS_STRIDE + rb + 8);
            mma16816(c[0][ni], a[0], bb);
            mma16816(c[1][ni], a[1], bb);
        }
    }
    __syncthreads();  // everyone done reading xs/Ws

    // stage C tile in smem fp16 for coalesced global store
    __half* cs = (__half*)sbuf;   // [128][136]
    #pragma unroll
    for (int mi = 0; mi < 2; mi++)
        #pragma unroll
        for (int ni = 0; ni < 8; ni++) {
            int r = wm * 32 + mi * 16 + gid;
            int e = wn * 64 + ni * 8 + qid * 2;
            *(__half2*)(cs + r * CS_STRIDE + e) =
                __floats2half2_rn(c[mi][ni][0], c[mi][ni][1]);
            *(__half2*)(cs + (r + 8) * CS_STRIDE + e) =
                __floats2half2_rn(c[mi][ni][2], c[mi][ni][3]);
        }
    __syncthreads();

    uint4* dst = (uint4*)(g_h + (size_t)t0 * E);
    #pragma unroll
    for (int it = 0; it < 8; it++) {
        int idx = tid + it * 256;   // 0..2047 uint4; 16 per row
        int row = idx >> 4;
        int c8  = idx & 15;
        dst[idx] = *(uint4*)(cs + row * CS_STRIDE + c8 * 8);
    }
}

// ---------------- K3: attention softmax + gather-weighted sum + head -------
// 256 thr = 8 warps, 1 token per warp; half-warp covers one row (LDG.128).
__global__ void __launch_bounds__(256) k3_out(const float* __restrict__ lin_W,
                                              const float* __restrict__ lin_b,
                                              float* __restrict__ y) {
    int tid = threadIdx.x;
    int wid = tid >> 5, lane = tid & 31;
    int t = blockIdx.x * 8 + wid;
    int b = t >> 10;
    int n = t & (N - 1);

    int   i  = g_idx[n * TOPK + lane];      // lane = k
    float ed = g_ed[(b << 10) + i];
    float es = g_es[t];
    float sc = es + ed;
    sc = sc >= 0.f ? sc : NEG_SLOPE * sc;

    float m = sc;
    #pragma unroll
    for (int o = 16; o; o >>= 1) m = fmaxf(m, __shfl_xor_sync(0xffffffffu, m, o));
    float p = __expf(sc - m);
    float s = p;
    #pragma unroll
    for (int o = 16; o; o >>= 1) s += __shfl_xor_sync(0xffffffffu, s, o);
    float alpha = p / s;

    const __half* hb = g_h + ((size_t)b << 10) * E;
    int hw = lane >> 4, sl = lane & 15;     // half-warp id, slice (e = sl*8..+8)

    // gather all (alpha, idx) for this half-warp's 16 k's up front
    float aw[16]; int idxs[16];
    #pragma unroll
    for (int j = 0; j < 16; j++) {
        int kk = j * 2 + hw;
        aw[j]   = __shfl_sync(0xffffffffu, alpha, kk);
        idxs[j] = __shfl_sync(0xffffffffu, i, kk);
    }

    float acc[8];
    #pragma unroll
    for (int q = 0; q < 8; q++) acc[q] = 0.f;

    // two batches of 8 loads -> MLP=8 in flight
    #pragma unroll
    for (int half = 0; half < 2; half++) {
        uint4 raw[8];
        #pragma unroll
        for (int j = 0; j < 8; j++)
            raw[j] = *(const uint4*)(hb + (size_t)idxs[half * 8 + j] * E + sl * 8);
        #pragma unroll
        for (int j = 0; j < 8; j++) {
            float a = aw[half * 8 + j];
            __half2* hp = (__half2*)&raw[j];
            #pragma unroll
            for (int q = 0; q < 4; q++) {
                float2 f = __half22float2(hp[q]);
                acc[q * 2]     += a * f.x;
                acc[q * 2 + 1] += a * f.y;
            }
        }
    }
    // combine even-k / odd-k halves
    #pragma unroll
    for (int q = 0; q < 8; q++) acc[q] += __shfl_xor_sync(0xffffffffu, acc[q], 16);

    const float4* lw4 = (const float4*)lin_W;
    float4 l0 = lw4[sl * 2], l1 = lw4[sl * 2 + 1];
    float part = fmaxf(acc[0], 0.f) * l0.x + fmaxf(acc[1], 0.f) * l0.y
               + fmaxf(acc[2], 0.f) * l0.z + fmaxf(acc[3], 0.f) * l0.w
               + fmaxf(acc[4], 0.f) * l1.x + fmaxf(acc[5], 0.f) * l1.y
               + fmaxf(acc[6], 0.f) * l1.z + fmaxf(acc[7], 0.f) * l1.w;
    #pragma unroll
    for (int o = 8; o; o >>= 1) part += __shfl_xor_sync(0xffffffffu, part, o);
    if (lane == 0) y[t] = part + lin_b[0];
}

// ---------------- launch ---------------------------------------------------
extern "C" void kernel_launch(void* const* d_in, const int* in_sizes, int n_in,
                              void* d_out, int out_size) {
    const float* x     = (const float*)d_in[0];
    const float* emb   = (const float*)d_in[1];
    const float* Wfe   = (const float*)d_in[2];
    const float* a_src = (const float*)d_in[3];
    const float* a_dst = (const float*)d_in[4];
    const float* lin_W = (const float*)d_in[5];
    const float* lin_b = (const float*)d_in[6];
    float* y = (float*)d_out;

    k0_ws<<<1, 128>>>(Wfe, a_src, a_dst);
    k1a_norm<<<N, 128>>>(emb, a_src, a_dst);
    k1b_topk<<<N / ROWS, 256>>>();
    k2_tc<<<(B * N) / 128, 256>>>(x, Wfe);
    k3_out<<<(B * N) / 8, 256>>>(lin_W, lin_b, y);
}